// round 6
// baseline (speedup 1.0000x reference)
#include <cuda_runtime.h>
#include <cuda_bf16.h>
#include <cstdint>

#define NN 12288
#define EE 196608
#define FIN 1433
#define NCH 45             // K chunks of 32:  45*32 = 1440 >= 1433
#define H1 32
#define H2 16
#define NC 7
#define XSTR 40            // x-tile row stride in bf16 elems (80 B, 16B-aligned rows)

// ---------------- scratch ----------------
__device__ __align__(16) float g_y[NN * H1];
__device__ __align__(16) float g_h[NN * H1];
__device__ __align__(16) float g_sg[NN * H1];
__device__ int   g_deg[NN];      // in-degree histogram (over col)
__device__ int   g_cnt[NN];      // out-degree histogram (over src)
__device__ int   g_ptr[NN + 1];  // CSR row pointers (by src)
__device__ int   g_fill[NN];     // CSR fill cursors
__device__ int   g_adj[EE];      // CSR adjacency (dst list)
__device__ float g_dis[NN];      // rsqrt(deg+1)
// W1^T split into bf16 hi/lo, pre-packed in mma-B fragment order:
// index ((c*32+n)*32+p), p encodes (s=k16-step, q=lane&3, j) -> klocal
__device__ __align__(16) __nv_bfloat16 g_whp[NCH * 32 * 32];
__device__ __align__(16) __nv_bfloat16 g_wlp[NCH * 32 * 32];

// ---------------- helpers ----------------
__device__ __forceinline__ uint32_t smem_u32(const void* p) {
    uint32_t a;
    asm("{ .reg .u64 t; cvta.to.shared.u64 t, %1; cvt.u32.u64 %0, t; }" : "=r"(a) : "l"(p));
    return a;
}

__device__ __forceinline__ void mma_bf16(float* c, const uint32_t* a,
                                         uint32_t b0, uint32_t b1) {
    asm volatile(
        "mma.sync.aligned.m16n8k16.row.col.f32.bf16.bf16.f32 "
        "{%0,%1,%2,%3}, {%4,%5,%6,%7}, {%8,%9}, {%0,%1,%2,%3};"
        : "+f"(c[0]), "+f"(c[1]), "+f"(c[2]), "+f"(c[3])
        : "r"(a[0]), "r"(a[1]), "r"(a[2]), "r"(a[3]), "r"(b0), "r"(b1));
}

#define LDMATRIX4(r0, r1, r2, r3, addr)                                        \
    asm volatile("ldmatrix.sync.aligned.m8n8.x4.shared.b16 {%0,%1,%2,%3}, [%4];" \
        : "=r"(r0), "=r"(r1), "=r"(r2), "=r"(r3) : "r"(addr))

__device__ __forceinline__ void split2(float c0, float c1, uint32_t& hi, uint32_t& lo) {
    __nv_bfloat162 hb = __floats2bfloat162_rn(c0, c1);
    float l0 = c0 - __bfloat162float(hb.x);
    float l1 = c1 - __bfloat162float(hb.y);
    __nv_bfloat162 lb = __floats2bfloat162_rn(l0, l1);
    hi = *(uint32_t*)&hb;
    lo = *(uint32_t*)&lb;
}

__device__ __forceinline__ int detect64(const void* ei, int* s_flag) {
    if (threadIdx.x < 32) {
        int ok = (((const int*)ei)[2 * threadIdx.x + 1] == 0);
        int all = __all_sync(0xffffffffu, ok);
        if (threadIdx.x == 0) *s_flag = all;
    }
    __syncthreads();
    return *s_flag;
}
__device__ __forceinline__ int eload(const void* ei, int is64, int which, int e) {
    if (is64) return (int)(((const long long*)ei)[(long long)which * EE + e]);
    return ((const int*)ei)[which * EE + e];
}

// ---------------- prep: W split + pack + zero histograms ----------------
__global__ void k_prep(const float* __restrict__ W1) {
    int idx = blockIdx.x * blockDim.x + threadIdx.x;   // 46080 threads
    if (idx < NCH * 32 * 32) {
        int c = idx >> 10, rem = idx & 1023;
        int n = rem >> 5, p = rem & 31;
        int s = p >> 4, q = (p >> 2) & 3, j = p & 3;
        int k = c * 32 + s * 16 + 2 * q + (j & 1) + ((j >> 1) & 1) * 8;
        float w = (k < FIN) ? W1[k * H1 + n] : 0.f;
        __nv_bfloat16 hb = __float2bfloat16_rn(w);
        float lo = w - __bfloat162float(hb);
        g_whp[idx] = hb;
        g_wlp[idx] = __float2bfloat16_rn(lo);
    }
    if (idx < NN) { g_deg[idx] = 0; g_cnt[idx] = 0; }
}

// ---------------- histograms ----------------
__global__ void k_count(const void* ei) {
    __shared__ int s64;
    int is64 = detect64(ei, &s64);
    int e = blockIdx.x * blockDim.x + threadIdx.x;
    if (e < EE) {
        atomicAdd(&g_deg[eload(ei, is64, 1, e)], 1);
        atomicAdd(&g_cnt[eload(ei, is64, 0, e)], 1);
    }
}

// ---------------- single-block scan + dis ----------------
__global__ void __launch_bounds__(1024) k_scan() {
    __shared__ int sm[1024];
    const int t = threadIdx.x;
    int local[12], s = 0;
    #pragma unroll
    for (int r = 0; r < 12; r++) {
        int i = t * 12 + r;
        local[r] = g_cnt[i];
        s += local[r];
        g_dis[i] = rsqrtf((float)(g_deg[i] + 1));
    }
    sm[t] = s;
    __syncthreads();
    #pragma unroll
    for (int off = 1; off < 1024; off <<= 1) {
        int v = (t >= off) ? sm[t - off] : 0;
        __syncthreads();
        sm[t] += v;
        __syncthreads();
    }
    int run = sm[t] - s;
    #pragma unroll
    for (int r = 0; r < 12; r++) {
        int i = t * 12 + r;
        g_ptr[i] = run;
        g_fill[i] = run;
        run += local[r];
    }
    if (t == 1023) g_ptr[NN] = EE;
}

// ---------------- CSR scatter ----------------
__global__ void k_scatter(const void* ei) {
    __shared__ int s64;
    int is64 = detect64(ei, &s64);
    int e = blockIdx.x * blockDim.x + threadIdx.x;
    if (e < EE) {
        int s = eload(ei, is64, 0, e);
        int d = eload(ei, is64, 1, e);
        int pos = atomicAdd(&g_fill[s], 1);
        g_adj[pos] = d;
    }
}

// ---------------- pipelined HMMA GEMM: y = x @ W1 ----------------
// grid 96, block 256 (8 warps). BM=128, BK=32 (2 k16 steps), double buffered.
struct __align__(16) SmemG {
    __nv_bfloat16 xh[2][128 * XSTR];   // 20480 B
    __nv_bfloat16 xl[2][128 * XSTR];   // 20480 B
    __nv_bfloat16 wh[2][32 * 32];      // 4096 B
    __nv_bfloat16 wl[2][32 * 32];      // 4096 B   total 49152 = 48 KB
};

__device__ __forceinline__ void ldg_x(const float* __restrict__ x, int row0,
                                      int c, int tid, float* f) {
    // pass p: row = p*16 + (tid>>4), colpair cp = tid&15 -> cols 2cp, 2cp+1
    const int rr = row0 + (tid >> 4);
    const int cp = tid & 15;
    const int k0 = c * 32 + 2 * cp;
    const bool m0 = (k0 < FIN), m1 = (k0 + 1 < FIN);
    #pragma unroll
    for (int p = 0; p < 8; p++) {
        const float* base = x + (long long)(rr + p * 16) * FIN + k0;
        f[2 * p]     = m0 ? __ldg(base)     : 0.f;
        f[2 * p + 1] = m1 ? __ldg(base + 1) : 0.f;
    }
}

__device__ __forceinline__ void sts_x(SmemG* sg, int st, int tid, const float* f) {
    const int r0 = tid >> 4;
    const int cp = tid & 15;
    #pragma unroll
    for (int p = 0; p < 8; p++) {
        uint32_t hi, lo;
        split2(f[2 * p], f[2 * p + 1], hi, lo);
        const int off = (r0 + p * 16) * XSTR + 2 * cp;
        *(uint32_t*)&sg->xh[st][off] = hi;
        *(uint32_t*)&sg->xl[st][off] = lo;
    }
}

__global__ void __launch_bounds__(256) k_gemm(const float* __restrict__ x) {
    __shared__ SmemG sg;
    const int tid = threadIdx.x, wid = tid >> 5, lane = tid & 31;
    const int row0 = blockIdx.x * 128;
    const int gid = lane >> 2, t2 = (lane & 3) * 2;

    float acc[4][4];
    #pragma unroll
    for (int nb = 0; nb < 4; nb++)
        #pragma unroll
        for (int q = 0; q < 4; q++) acc[nb][q] = 0.f;

    float f[2][16];
    uint4 wreg;
    const int wt = tid & 127;                 // 128-thread W copier id
    const bool whalf = (tid < 128);

    // prologue: chunk0 -> stage0, prefetch chunk1
    ldg_x(x, row0, 0, tid, f[0]);
    {
        uint4 v = whalf ? ((const uint4*)g_whp)[wt] : ((const uint4*)g_wlp)[wt];
        if (whalf) ((uint4*)sg.wh[0])[wt] = v;
        else       ((uint4*)sg.wl[0])[wt] = v;
    }
    sts_x(&sg, 0, tid, f[0]);
    ldg_x(x, row0, 1, tid, f[1]);
    wreg = whalf ? ((const uint4*)g_whp)[128 + wt] : ((const uint4*)g_wlp)[128 + wt];
    __syncthreads();

    const uint32_t xh_b = smem_u32(&sg.xh[0][0]);
    const uint32_t xl_b = smem_u32(&sg.xl[0][0]);
    const uint32_t wh_b = smem_u32(&sg.wh[0][0]);
    const uint32_t wl_b = smem_u32(&sg.wl[0][0]);
    const uint32_t lrow = (lane & 15), lhalf = (lane >> 4);

    for (int c = 0; c < NCH; c++) {
        const int st = c & 1, nst = st ^ 1;
        if (c + 2 < NCH) ldg_x(x, row0, c + 2, tid, f[c & 1]);

        // compute chunk c from stage st
        const uint32_t xbaseH = xh_b + st * (128 * XSTR * 2);
        const uint32_t xbaseL = xl_b + st * (128 * XSTR * 2);
        const uint32_t wbaseH = wh_b + st * (32 * 32 * 2);
        const uint32_t wbaseL = wl_b + st * (32 * 32 * 2);
        const uint32_t arow = (wid * 16 + lrow) * (XSTR * 2) + lhalf * 16;
        #pragma unroll
        for (int s = 0; s < 2; s++) {
            uint32_t ah[4], al[4];
            LDMATRIX4(ah[0], ah[1], ah[2], ah[3], xbaseH + arow + s * 32);
            LDMATRIX4(al[0], al[1], al[2], al[3], xbaseL + arow + s * 32);
            #pragma unroll
            for (int nb = 0; nb < 4; nb++) {
                const uint32_t boff = (nb * 8 + gid) * 64 + s * 32 + (lane & 3) * 8;
                uint32_t bh0, bh1, bl0, bl1;
                asm volatile("ld.shared.v2.b32 {%0,%1}, [%2];"
                             : "=r"(bh0), "=r"(bh1) : "r"(wbaseH + boff));
                asm volatile("ld.shared.v2.b32 {%0,%1}, [%2];"
                             : "=r"(bl0), "=r"(bl1) : "r"(wbaseL + boff));
                mma_bf16(acc[nb], ah, bh0, bh1);
                mma_bf16(acc[nb], al, bh0, bh1);
                mma_bf16(acc[nb], ah, bl0, bl1);
            }
        }

        if (c + 1 < NCH) {
            sts_x(&sg, nst, tid, f[(c + 1) & 1]);
            if (whalf) ((uint4*)sg.wh[nst])[wt] = wreg;
            else       ((uint4*)sg.wl[nst])[wt] = wreg;
        }
        if (c + 2 < NCH)
            wreg = whalf ? ((const uint4*)g_whp)[(c + 2) * 128 + wt]
                         : ((const uint4*)g_wlp)[(c + 2) * 128 + wt];
        __syncthreads();
    }

    const int r0 = row0 + wid * 16 + gid;
    #pragma unroll
    for (int nb = 0; nb < 4; nb++) {
        *(float2*)&g_y[r0 * H1 + nb * 8 + t2]       = make_float2(acc[nb][0], acc[nb][1]);
        *(float2*)&g_y[(r0 + 8) * H1 + nb * 8 + t2] = make_float2(acc[nb][2], acc[nb][3]);
    }
}

// ---------------- GCN gather + h (warp per node) ----------------
__global__ void __launch_bounds__(256) k_gcn_h(const float* __restrict__ b1) {
    const int wid = threadIdx.x >> 5, lane = threadIdx.x & 31;
    const int i = blockIdx.x * 8 + wid;
    const int p0 = g_ptr[i], p1 = g_ptr[i + 1];
    const int n = p1 - p0;

    int   aj = 0;
    float sv = 0.f;
    if (lane < n) { aj = g_adj[p0 + lane]; sv = g_dis[aj]; }

    float acc = 0.f;
    const int nn = min(n, 32);
    for (int j = 0; j < nn; j++) {
        int   d = __shfl_sync(0xffffffffu, aj, j);
        float s = __shfl_sync(0xffffffffu, sv, j);
        acc += s * g_y[d * H1 + lane];
    }
    for (int j = p0 + 32; j < p1; j++) {
        int d = g_adj[j];
        acc += g_dis[d] * g_y[d * H1 + lane];
    }
    const float di = g_dis[i];
    float v = di * (acc + di * g_y[i * H1 + lane]) + b1[lane];
    g_h[i * H1 + lane] = fmaxf(v, 0.f);
}

// ---------------- SAGE gather + mean (warp per node) ----------------
__global__ void __launch_bounds__(256) k_sage() {
    const int wid = threadIdx.x >> 5, lane = threadIdx.x & 31;
    const int i = blockIdx.x * 8 + wid;
    const int p0 = g_ptr[i], p1 = g_ptr[i + 1];
    const int n = p1 - p0;

    int aj = 0;
    if (lane < n) aj = g_adj[p0 + lane];

    float acc = 0.f;
    const int nn = min(n, 32);
    for (int j = 0; j < nn; j++) {
        int d = __shfl_sync(0xffffffffu, aj, j);
        acc += g_h[d * H1 + lane];
    }
    for (int j = p0 + 32; j < p1; j++)
        acc += g_h[g_adj[j] * H1 + lane];

    const float invc = (n > 0) ? (1.0f / (float)n) : 0.f;
    g_sg[i * H1 + lane] = acc * invc;
}

// ---------------- head ----------------
__global__ void __launch_bounds__(256) k_head(const float* __restrict__ Wl,
                                              const float* __restrict__ bl,
                                              const float* __restrict__ Wr,
                                              const float* __restrict__ br,
                                              const float* __restrict__ W3,
                                              const float* __restrict__ b3,
                                              float* __restrict__ out) {
    __shared__ float sWl[H1 * H2], sWr[H1 * H2], sW3[H2 * NC];
    __shared__ float sbl[H2], sbr[H2], sb3[NC];
    const int tid = threadIdx.x;
    for (int i = tid; i < H1 * H2; i += blockDim.x) { sWl[i] = Wl[i]; sWr[i] = Wr[i]; }
    for (int i = tid; i < H2 * NC; i += blockDim.x) sW3[i] = W3[i];
    if (tid < H2) { sbl[tid] = bl[tid]; sbr[tid] = br[tid]; }
    if (tid < NC) sb3[tid] = b3[tid];
    __syncthreads();

    const int n = blockIdx.x * blockDim.x + tid;
    if (n >= NN) return;

    float t[H2];
    #pragma unroll
    for (int j = 0; j < H2; j++) t[j] = sbl[j] + sbr[j];
    #pragma unroll 4
    for (int c = 0; c < H1; c++) {
        const float hv = g_h[n * H1 + c];
        const float av = g_sg[n * H1 + c];
        #pragma unroll
        for (int j = 0; j < H2; j++)
            t[j] += hv * sWl[c * H2 + j] + av * sWr[c * H2 + j];
    }
    float ss = 0.f;
    #pragma unroll
    for (int j = 0; j < H2; j++) { t[j] = fmaxf(t[j], 0.f); ss += t[j] * t[j]; }
    const float sc = 1.0f / (sqrtf(ss) + 1e-6f);

    float lg[NC];
    #pragma unroll
    for (int k = 0; k < NC; k++) lg[k] = sb3[k];
    #pragma unroll
    for (int j = 0; j < H2; j++) {
        const float tv = t[j] * sc;
        #pragma unroll
        for (int k = 0; k < NC; k++) lg[k] += tv * sW3[j * NC + k];
    }
    float mx = lg[0];
    #pragma unroll
    for (int k = 1; k < NC; k++) mx = fmaxf(mx, lg[k]);
    float se = 0.f;
    #pragma unroll
    for (int k = 0; k < NC; k++) { lg[k] = __expf(lg[k] - mx); se += lg[k]; }
    const float inv = 1.0f / se;
    #pragma unroll
    for (int k = 0; k < NC; k++) out[n * NC + k] = lg[k] * inv;
}

extern "C" void kernel_launch(void* const* d_in, const int* in_sizes, int n_in,
                              void* d_out, int out_size) {
    const float* x  = (const float*)d_in[0];
    const void*  ei = d_in[1];
    const float* W1 = (const float*)d_in[2];
    const float* b1 = (const float*)d_in[3];
    const float* Wl = (const float*)d_in[4];
    const float* bl = (const float*)d_in[5];
    const float* Wr = (const float*)d_in[6];
    const float* br = (const float*)d_in[7];
    const float* W3 = (const float*)d_in[8];
    const float* b3 = (const float*)d_in[9];
    float* out = (float*)d_out;

    k_prep<<<(NCH * 32 * 32 + 255) / 256, 256>>>(W1);
    k_count<<<EE / 256, 256>>>(ei);
    k_scan<<<1, 1024>>>();
    k_scatter<<<EE / 256, 256>>>(ei);
    k_gemm<<<NN / 128, 256>>>(x);
    k_gcn_h<<<NN / 8, 256>>>(b1);
    k_sage<<<NN / 8, 256>>>();
    k_head<<<NN / 256, 256>>>(Wl, bl, Wr, br, W3, b3, out);
}

// round 7
// speedup vs baseline: 2.9189x; 2.9189x over previous
#include <cuda_runtime.h>
#include <cuda_bf16.h>
#include <cstdint>

#define NN 12288
#define EE 196608
#define FIN 1433
#define NST16 90           // 90 k16-steps: 90*16 = 1440 >= 1433
#define KSPL 5             // split-K factor: 5 * 18 steps
#define SPS 18             // k16-steps per split
#define H1 32
#define H2 16
#define NC 7

// ---------------- scratch ----------------
__device__ __align__(16) float g_y[NN * H1];
__device__ __align__(16) float g_acc[NN * H1];
__device__ __align__(16) float g_h[NN * H1];
__device__ __align__(16) float g_sg[NN * H1];
__device__ int   g_deg[NN];
__device__ int   g_cnt[NN];
// W1^T split bf16 hi/lo, packed in B-fragment order:
// element ((c*32+n)*32 + q*4 + j), j=0..3 -> k = 16c + 2q + (j&1) + (j>>1)*8
__device__ __align__(16) __nv_bfloat16 g_whp[NST16 * 32 * 32];
__device__ __align__(16) __nv_bfloat16 g_wlp[NST16 * 32 * 32];

// ---------------- helpers ----------------
__device__ __forceinline__ void red4(float* p, float4 v) {
    asm volatile("red.global.add.v4.f32 [%0], {%1,%2,%3,%4};"
                 :: "l"(p), "f"(v.x), "f"(v.y), "f"(v.z), "f"(v.w) : "memory");
}
__device__ __forceinline__ void red2(float* p, float a, float b) {
    asm volatile("red.global.add.v2.f32 [%0], {%1,%2};"
                 :: "l"(p), "f"(a), "f"(b) : "memory");
}

__device__ __forceinline__ void mma_bf16(float* c, const uint32_t* a,
                                         uint32_t b0, uint32_t b1) {
    asm volatile(
        "mma.sync.aligned.m16n8k16.row.col.f32.bf16.bf16.f32 "
        "{%0,%1,%2,%3}, {%4,%5,%6,%7}, {%8,%9}, {%0,%1,%2,%3};"
        : "+f"(c[0]), "+f"(c[1]), "+f"(c[2]), "+f"(c[3])
        : "r"(a[0]), "r"(a[1]), "r"(a[2]), "r"(a[3]), "r"(b0), "r"(b1));
}

__device__ __forceinline__ void split2(float c0, float c1, uint32_t& hi, uint32_t& lo) {
    __nv_bfloat162 hb = __floats2bfloat162_rn(c0, c1);
    float l0 = c0 - __bfloat162float(hb.x);
    float l1 = c1 - __bfloat162float(hb.y);
    __nv_bfloat162 lb = __floats2bfloat162_rn(l0, l1);
    hi = *(uint32_t*)&hb;
    lo = *(uint32_t*)&lb;
}

__device__ __forceinline__ int detect64(const void* ei, int* s_flag) {
    if (threadIdx.x < 32) {
        int ok = (((const int*)ei)[2 * threadIdx.x + 1] == 0);
        int all = __all_sync(0xffffffffu, ok);
        if (threadIdx.x == 0) *s_flag = all;
    }
    __syncthreads();
    return *s_flag;
}
__device__ __forceinline__ int eload(const void* ei, int is64, int which, int e) {
    if (is64) return (int)(((const long long*)ei)[(long long)which * EE + e]);
    return ((const int*)ei)[which * EE + e];
}

// ---------------- prep: W split+pack, zero y/acc/sg, init deg/cnt ----------------
__global__ void k_prep(const float* __restrict__ W1) {
    int idx = blockIdx.x * blockDim.x + threadIdx.x;   // NN*H1 = 393216 threads
    if (idx < NST16 * 32 * 32) {
        int c = idx >> 10, rem = idx & 1023;
        int n = rem >> 5, p = rem & 31;
        int q = p >> 2, j = p & 3;
        int k = c * 16 + 2 * q + (j & 1) + ((j >> 1) & 1) * 8;
        float w = (k < FIN) ? W1[k * H1 + n] : 0.f;
        __nv_bfloat16 hb = __float2bfloat16_rn(w);
        float lo = w - __bfloat162float(hb);
        g_whp[idx] = hb;
        g_wlp[idx] = __float2bfloat16_rn(lo);
    }
    if (idx < NN) { g_deg[idx] = 1; g_cnt[idx] = 0; }   // deg starts at 1 (self loop)
    if (idx < NN * H1) { g_y[idx] = 0.f; g_acc[idx] = 0.f; g_sg[idx] = 0.f; }
}

// ---------------- degree / out-count ----------------
__global__ void k_count(const void* ei) {
    __shared__ int s64;
    int is64 = detect64(ei, &s64);
    int e = blockIdx.x * blockDim.x + threadIdx.x;
    if (e < EE) {
        atomicAdd(&g_deg[eload(ei, is64, 1, e)], 1);
        atomicAdd(&g_cnt[eload(ei, is64, 0, e)], 1);
    }
}

// ---------------- split-K HMMA GEMM: y += x @ W1 (bf16 3-term) ----------------
// grid (96, 5), block 256. Warp: 16 rows x 32 cols, 18 k16-steps, reg-resident.
__device__ __forceinline__ void ldx8(const float* __restrict__ xr0,
                                     const float* __restrict__ xr1,
                                     int c0, float* f) {
    const bool m0 = (c0     < FIN), m1 = (c0 + 1 < FIN);
    const bool m8 = (c0 + 8 < FIN), m9 = (c0 + 9 < FIN);
    f[0] = m0 ? __ldg(xr0 + c0)     : 0.f;
    f[1] = m1 ? __ldg(xr0 + c0 + 1) : 0.f;
    f[2] = m0 ? __ldg(xr1 + c0)     : 0.f;
    f[3] = m1 ? __ldg(xr1 + c0 + 1) : 0.f;
    f[4] = m8 ? __ldg(xr0 + c0 + 8) : 0.f;
    f[5] = m9 ? __ldg(xr0 + c0 + 9) : 0.f;
    f[6] = m8 ? __ldg(xr1 + c0 + 8) : 0.f;
    f[7] = m9 ? __ldg(xr1 + c0 + 9) : 0.f;
}

__global__ void __launch_bounds__(256) k_gemm(const float* __restrict__ x) {
    const int tid = threadIdx.x, wid = tid >> 5, lane = tid & 31;
    const int gid = lane >> 2;
    const int q   = lane & 3;
    const int t2  = q * 2;
    const int r0  = blockIdx.x * 128 + wid * 16 + gid;
    const int r1  = r0 + 8;
    const float* xr0 = x + (long long)r0 * FIN;
    const float* xr1 = x + (long long)r1 * FIN;
    const int sbase = blockIdx.y * SPS;

    float acc[4][4];
    #pragma unroll
    for (int nb = 0; nb < 4; nb++)
        #pragma unroll
        for (int p = 0; p < 4; p++) acc[nb][p] = 0.f;

    float cur[8], nxt[8];
    ldx8(xr0, xr1, sbase * 16 + t2, cur);

    for (int s = 0; s < SPS; s++) {
        const int c = sbase + s;
        if (s + 1 < SPS) ldx8(xr0, xr1, (c + 1) * 16 + t2, nxt);

        uint32_t ah[4], al[4];
        split2(cur[0], cur[1], ah[0], al[0]);
        split2(cur[2], cur[3], ah[1], al[1]);
        split2(cur[4], cur[5], ah[2], al[2]);
        split2(cur[6], cur[7], ah[3], al[3]);

        #pragma unroll
        for (int nb = 0; nb < 4; nb++) {
            const int n = nb * 8 + gid;
            const uint2 bh = __ldg((const uint2*)g_whp + (c * 32 + n) * 8 + q);
            const uint2 bl = __ldg((const uint2*)g_wlp + (c * 32 + n) * 8 + q);
            mma_bf16(acc[nb], ah, bh.x, bh.y);
            mma_bf16(acc[nb], al, bh.x, bh.y);
            mma_bf16(acc[nb], ah, bl.x, bl.y);
        }
        #pragma unroll
        for (int p = 0; p < 8; p++) cur[p] = nxt[p];
    }

    #pragma unroll
    for (int nb = 0; nb < 4; nb++) {
        red2(&g_y[r0 * H1 + nb * 8 + t2], acc[nb][0], acc[nb][1]);
        red2(&g_y[r1 * H1 + nb * 8 + t2], acc[nb][2], acc[nb][3]);
    }
}

// ---------------- GCN edge aggregation (v4 red) ----------------
__global__ void k_gcn(const void* ei) {
    __shared__ int s64;
    int is64 = detect64(ei, &s64);
    int idx = blockIdx.x * blockDim.x + threadIdx.x;   // EE*8 threads
    int e = idx >> 3, g = idx & 7;
    int r  = eload(ei, is64, 0, e);
    int cl = eload(ei, is64, 1, e);
    float s = rsqrtf((float)g_deg[cl]);
    float4 v = *(const float4*)&g_y[cl * H1 + g * 4];
    v.x *= s; v.y *= s; v.z *= s; v.w *= s;
    red4(&g_acc[r * H1 + g * 4], v);
}

// ---------------- h = relu(dis*(acc + dis*y) + b1) ----------------
__global__ void k_h(const float* __restrict__ b1) {
    int idx = blockIdx.x * blockDim.x + threadIdx.x;   // NN*8
    int i = idx >> 3, g = idx & 7;
    float d = rsqrtf((float)g_deg[i]);
    float4 a = *(const float4*)&g_acc[idx * 4];
    float4 y = *(const float4*)&g_y[idx * 4];
    float4 b = *(const float4*)&b1[g * 4];
    float4 o;
    o.x = fmaxf(d * (a.x + d * y.x) + b.x, 0.f);
    o.y = fmaxf(d * (a.y + d * y.y) + b.y, 0.f);
    o.z = fmaxf(d * (a.z + d * y.z) + b.z, 0.f);
    o.w = fmaxf(d * (a.w + d * y.w) + b.w, 0.f);
    *(float4*)&g_h[idx * 4] = o;
}

// ---------------- SAGE aggregation (v4 red) ----------------
__global__ void k_sage(const void* ei) {
    __shared__ int s64;
    int is64 = detect64(ei, &s64);
    int idx = blockIdx.x * blockDim.x + threadIdx.x;
    int e = idx >> 3, g = idx & 7;
    int s = eload(ei, is64, 0, e);
    int d = eload(ei, is64, 1, e);
    float4 v = *(const float4*)&g_h[d * H1 + g * 4];
    red4(&g_sg[s * H1 + g * 4], v);
}

// ---------------- head ----------------
__global__ void __launch_bounds__(256) k_head(const float* __restrict__ Wl,
                                              const float* __restrict__ bl,
                                              const float* __restrict__ Wr,
                                              const float* __restrict__ br,
                                              const float* __restrict__ W3,
                                              const float* __restrict__ b3,
                                              float* __restrict__ out) {
    __shared__ float sWl[H1 * H2], sWr[H1 * H2], sW3[H2 * NC];
    __shared__ float sbl[H2], sbr[H2], sb3[NC];
    const int tid = threadIdx.x;
    for (int i = tid; i < H1 * H2; i += blockDim.x) { sWl[i] = Wl[i]; sWr[i] = Wr[i]; }
    for (int i = tid; i < H2 * NC; i += blockDim.x) sW3[i] = W3[i];
    if (tid < H2) { sbl[tid] = bl[tid]; sbr[tid] = br[tid]; }
    if (tid < NC) sb3[tid] = b3[tid];
    __syncthreads();

    const int n = blockIdx.x * blockDim.x + tid;
    if (n >= NN) return;
    const float invc = 1.0f / fmaxf((float)g_cnt[n], 1.0f);

    float t[H2];
    #pragma unroll
    for (int j = 0; j < H2; j++) t[j] = sbl[j] + sbr[j];
    #pragma unroll 4
    for (int c = 0; c < H1; c++) {
        const float hv = g_h[n * H1 + c];
        const float av = g_sg[n * H1 + c] * invc;
        #pragma unroll
        for (int j = 0; j < H2; j++)
            t[j] += hv * sWl[c * H2 + j] + av * sWr[c * H2 + j];
    }
    float ss = 0.f;
    #pragma unroll
    for (int j = 0; j < H2; j++) { t[j] = fmaxf(t[j], 0.f); ss += t[j] * t[j]; }
    const float sc = 1.0f / (sqrtf(ss) + 1e-6f);

    float lg[NC];
    #pragma unroll
    for (int k = 0; k < NC; k++) lg[k] = sb3[k];
    #pragma unroll
    for (int j = 0; j < H2; j++) {
        const float tv = t[j] * sc;
        #pragma unroll
        for (int k = 0; k < NC; k++) lg[k] += tv * sW3[j * NC + k];
    }
    float mx = lg[0];
    #pragma unroll
    for (int k = 1; k < NC; k++) mx = fmaxf(mx, lg[k]);
    float se = 0.f;
    #pragma unroll
    for (int k = 0; k < NC; k++) { lg[k] = __expf(lg[k] - mx); se += lg[k]; }
    const float inv = 1.0f / se;
    #pragma unroll
    for (int k = 0; k < NC; k++) out[n * NC + k] = lg[k] * inv;
}

extern "C" void kernel_launch(void* const* d_in, const int* in_sizes, int n_in,
                              void* d_out, int out_size) {
    const float* x  = (const float*)d_in[0];
    const void*  ei = d_in[1];
    const float* W1 = (const float*)d_in[2];
    const float* b1 = (const float*)d_in[3];
    const float* Wl = (const float*)d_in[4];
    const float* bl = (const float*)d_in[5];
    const float* Wr = (const float*)d_in[6];
    const float* br = (const float*)d_in[7];
    const float* W3 = (const float*)d_in[8];
    const float* b3 = (const float*)d_in[9];
    float* out = (float*)d_out;

    k_prep<<<(NN * H1 + 255) / 256, 256>>>(W1);
    k_count<<<EE / 256, 256>>>(ei);
    k_gemm<<<dim3(NN / 128, KSPL), 256>>>(x);
    k_gcn<<<(EE * 8) / 256, 256>>>(ei);
    k_h<<<(NN * 8) / 256, 256>>>(b1);
    k_sage<<<(EE * 8) / 256, 256>>>(ei);
    k_head<<<(NN + 255) / 256, 256>>>(Wl, bl, Wr, br, W3, b3, out);
}